// round 7
// baseline (speedup 1.0000x reference)
#include <cuda_runtime.h>
#include <cstdint>
#include <cstddef>

#define T_DIM 2048
#define B_DIM 32
#define E_DIM 512
#define N_DIM 512
#define K_DIM 512
#define M_DIM (T_DIM * B_DIM)   // 65536 rows, row m = t*B + b

// ---------------- device scratch ----------------
__device__ float g_w[M_DIM];
__device__ int   g_len[B_DIM];
__device__ int   g_nrows[B_DIM];
__device__ int   g_rt0[B_DIM * T_DIM];
__device__ int   g_rt1[B_DIM * T_DIM];
__device__ float g_rc0[B_DIM * T_DIM];
__device__ float g_rc1[B_DIM * T_DIM];
__device__ float g_rmult[B_DIM * T_DIM];

// ---------------- f32x2 helpers ----------------
typedef unsigned long long u64;
__device__ __forceinline__ u64 fma2(u64 a, u64 b, u64 c) {
    u64 d;
    asm("fma.rn.f32x2 %0, %1, %2, %3;" : "=l"(d) : "l"(a), "l"(b), "l"(c));
    return d;
}
__device__ __forceinline__ u64 dupf(float a) {
    u64 d;
    asm("mov.b64 %0, {%1, %1};" : "=l"(d) : "f"(a));
    return d;
}
__device__ __forceinline__ void unpk(u64 v, float& lo, float& hi) {
    asm("mov.b64 {%0, %1}, %2;" : "=f"(lo), "=f"(hi) : "l"(v));
}

// ---------------- K0: mask dtype detection + lengths ------------------------
__global__ void k0_mask(const void* __restrict__ mask) {
    __shared__ int flags[3];
    int tid = threadIdx.x;
    if (tid < 3) flags[tid] = 0;
    __syncthreads();
    const unsigned* dw = (const unsigned*)mask;
    for (int i = tid; i < 16384; i += blockDim.x) {
        unsigned d = dw[i];
        if (d != 0u) {
            if (d == 1u)                flags[0] = 1;
            else if (d == 0x3F800000u)  flags[1] = 1;
            else                        flags[2] = 1;
        }
    }
    __syncthreads();
    int kind = flags[2] ? 2 : (flags[1] ? 1 : 0);
    int warp = tid >> 5, lane = tid & 31;
    int cnt = 0;
    if (kind == 2) {
        const unsigned char* p = (const unsigned char*)mask + warp * T_DIM;
        for (int t = lane; t < T_DIM; t += 32) cnt += (p[t] == 0);
    } else {
        const unsigned* p = dw + (size_t)warp * T_DIM;
        for (int t = lane; t < T_DIM; t += 32) cnt += (p[t] == 0u);
    }
    for (int o = 16; o > 0; o >>= 1) cnt += __shfl_down_sync(0xffffffffu, cnt, o);
    if (lane == 0) g_len[warp] = cnt;
}

// ---------------- K1: fused fp32 GEMM, FFMA2 with paired-M accumulators -----
// acc pair = (C[m][n], C[m+1][n]); A m-pairs direct LDS.64; B duplicated in
// smem at store time -> broadcast operand is a direct 64-bit load. No MOVs in
// the inner loop.
#define BMT 128
#define BNT 128
#define BKT 16
#define KTILES (K_DIM / BKT)   // 32
#define AS_STR 132             // 128 + 4 pad
#define BG_STR 20              // 16 data floats (8 dup pairs) + 4 pad
#define BROW_STR (16 * BG_STR) // 320 floats per k-row
// dynamic smem (floats): As 2*16*132=4224 | Bsd 2*16*320=10240 | red 128*17=2176
#define OFF_BS 4224
#define OFF_RED 14464
#define SMF 16640
#define SM_BYTES (SMF * 4)

__global__ __launch_bounds__(256, 2) void k1_gemm(
    const float* __restrict__ A,   // [M][K] row-major
    const float* __restrict__ W1,  // [K][N] row-major
    const float* __restrict__ b1,  // [N]
    const float* __restrict__ w2,  // [N]
    const float* __restrict__ b2)  // [1]
{
    extern __shared__ float smf[];
    float* As  = smf;            // [2][16][132]
    float* Bsd = smf + OFF_BS;   // [2][16][320]
    float* red = smf + OFF_RED;  // [128][17]

    const int tid = threadIdx.x;
    const int tx = tid & 15, ty = tid >> 4;
    const int m0 = blockIdx.x * BMT;

    // A loads: 512 float4 per k-tile, 2 per thread (transpose-store)
    const int aRow0 = tid >> 2;
    const int aRow1 = aRow0 + 64;
    const int aCol  = (tid & 3) * 4;
    // B loads: 2 float4 per thread per k-tile, stored duplicated
    const int bRow0 = tid >> 5;
    const int bRow1 = bRow0 + 8;
    const int bCol  = (tid & 31) * 4;
    const int bGrp  = (bCol >> 3) * BG_STR + (bCol & 7) * 2;

    float rowacc[8];
#pragma unroll
    for (int i = 0; i < 8; i++) rowacc[i] = 0.f;
    const float b2s = b2[0];
    __syncthreads();

    for (int n0 = 0; n0 < N_DIM; n0 += BNT) {
        u64 acc2[4][8];
#pragma unroll
        for (int mp = 0; mp < 4; mp++)
#pragma unroll
            for (int j = 0; j < 8; j++) acc2[mp][j] = 0ull;

        float4 aR0, aR1, bR0, bR1;
        // prologue: tile 0 -> buf 0
        aR0 = *(const float4*)(A + (size_t)(m0 + aRow0) * K_DIM + aCol);
        aR1 = *(const float4*)(A + (size_t)(m0 + aRow1) * K_DIM + aCol);
        bR0 = *(const float4*)(W1 + (size_t)bRow0 * N_DIM + n0 + bCol);
        bR1 = *(const float4*)(W1 + (size_t)bRow1 * N_DIM + n0 + bCol);
        As[(aCol + 0) * AS_STR + aRow0] = aR0.x; As[(aCol + 1) * AS_STR + aRow0] = aR0.y;
        As[(aCol + 2) * AS_STR + aRow0] = aR0.z; As[(aCol + 3) * AS_STR + aRow0] = aR0.w;
        As[(aCol + 0) * AS_STR + aRow1] = aR1.x; As[(aCol + 1) * AS_STR + aRow1] = aR1.y;
        As[(aCol + 2) * AS_STR + aRow1] = aR1.z; As[(aCol + 3) * AS_STR + aRow1] = aR1.w;
        {
            u64* q0 = (u64*)(Bsd + bRow0 * BROW_STR + bGrp);
            q0[0] = dupf(bR0.x); q0[1] = dupf(bR0.y); q0[2] = dupf(bR0.z); q0[3] = dupf(bR0.w);
            u64* q1 = (u64*)(Bsd + bRow1 * BROW_STR + bGrp);
            q1[0] = dupf(bR1.x); q1[1] = dupf(bR1.y); q1[2] = dupf(bR1.z); q1[3] = dupf(bR1.w);
        }
        __syncthreads();

        for (int kt = 0; kt < KTILES; kt++) {
            const int cur = kt & 1;
            if (kt + 1 < KTILES) {
                const int kb = (kt + 1) * BKT;
                aR0 = *(const float4*)(A + (size_t)(m0 + aRow0) * K_DIM + kb + aCol);
                aR1 = *(const float4*)(A + (size_t)(m0 + aRow1) * K_DIM + kb + aCol);
                bR0 = *(const float4*)(W1 + (size_t)(kb + bRow0) * N_DIM + n0 + bCol);
                bR1 = *(const float4*)(W1 + (size_t)(kb + bRow1) * N_DIM + n0 + bCol);
            }
            const float* Ac = As + cur * (BKT * AS_STR);
            const float* Bc = Bsd + cur * (BKT * BROW_STR);
#pragma unroll
            for (int kk = 0; kk < BKT; kk++) {
                const u64* ap = (const u64*)(Ac + kk * AS_STR + ty * 8);
                const u64* bp = (const u64*)(Bc + kk * BROW_STR + tx * BG_STR);
                u64 a0 = ap[0], a1 = ap[1], a2 = ap[2], a3 = ap[3];
                u64 b0 = bp[0], b1v = bp[1], b2v = bp[2], b3v = bp[3];
                u64 b4 = bp[4], b5 = bp[5], b6 = bp[6], b7 = bp[7];
#pragma unroll
                for (int mp = 0; mp < 4; mp++) {
                    u64 av = (mp == 0) ? a0 : (mp == 1) ? a1 : (mp == 2) ? a2 : a3;
                    acc2[mp][0] = fma2(av, b0,  acc2[mp][0]);
                    acc2[mp][1] = fma2(av, b1v, acc2[mp][1]);
                    acc2[mp][2] = fma2(av, b2v, acc2[mp][2]);
                    acc2[mp][3] = fma2(av, b3v, acc2[mp][3]);
                    acc2[mp][4] = fma2(av, b4,  acc2[mp][4]);
                    acc2[mp][5] = fma2(av, b5,  acc2[mp][5]);
                    acc2[mp][6] = fma2(av, b6,  acc2[mp][6]);
                    acc2[mp][7] = fma2(av, b7,  acc2[mp][7]);
                }
            }
            if (kt + 1 < KTILES) {
                const int nb = cur ^ 1;
                float* An = As + nb * (BKT * AS_STR);
                float* Bn = Bsd + nb * (BKT * BROW_STR);
                An[(aCol + 0) * AS_STR + aRow0] = aR0.x; An[(aCol + 1) * AS_STR + aRow0] = aR0.y;
                An[(aCol + 2) * AS_STR + aRow0] = aR0.z; An[(aCol + 3) * AS_STR + aRow0] = aR0.w;
                An[(aCol + 0) * AS_STR + aRow1] = aR1.x; An[(aCol + 1) * AS_STR + aRow1] = aR1.y;
                An[(aCol + 2) * AS_STR + aRow1] = aR1.z; An[(aCol + 3) * AS_STR + aRow1] = aR1.w;
                u64* q0 = (u64*)(Bn + bRow0 * BROW_STR + bGrp);
                q0[0] = dupf(bR0.x); q0[1] = dupf(bR0.y); q0[2] = dupf(bR0.z); q0[3] = dupf(bR0.w);
                u64* q1 = (u64*)(Bn + bRow1 * BROW_STR + bGrp);
                q1[0] = dupf(bR1.x); q1[1] = dupf(bR1.y); q1[2] = dupf(bR1.z); q1[3] = dupf(bR1.w);
                __syncthreads();
            }
        }

        // fused epilogue: relu(c + b1) * w2 -> row partials
        float b1r[8], w2r[8];
#pragma unroll
        for (int j = 0; j < 8; j++) {
            b1r[j] = b1[n0 + tx * 8 + j];
            w2r[j] = w2[n0 + tx * 8 + j];
        }
#pragma unroll
        for (int mp = 0; mp < 4; mp++)
#pragma unroll
            for (int j = 0; j < 8; j++) {
                float clo, chi;
                unpk(acc2[mp][j], clo, chi);
                float h0 = fmaxf(clo + b1r[j], 0.f);
                float h1 = fmaxf(chi + b1r[j], 0.f);
                rowacc[mp * 2 + 0] = fmaf(h0, w2r[j], rowacc[mp * 2 + 0]);
                rowacc[mp * 2 + 1] = fmaf(h1, w2r[j], rowacc[mp * 2 + 1]);
            }
        __syncthreads();  // before next n-tile's prologue reuses buf 0
    }

    // reduce rowacc across the 16 tx threads of each row (fixed order)
#pragma unroll
    for (int i = 0; i < 8; i++) red[(ty * 8 + i) * 17 + tx] = rowacc[i];
    __syncthreads();
    if (tid < BMT) {
        float s = 0.f;
#pragma unroll
        for (int x = 0; x < 16; x++) s += red[tid * 17 + x];
        float arg = s + b2s;
        g_w[m0 + tid] = 1.0f / (1.0f + expf(-arg));
    }
}

// ---------------- K2: scalar CIF scan per batch -----------------------------
__global__ void k2_scan(float* __restrict__ out_marks,
                        float* __restrict__ out_quantity,
                        int write_extras)
{
    const int b = blockIdx.x;
    const int lane = threadIdx.x;
    const int L = g_len[b];

    float prev_w = 0.f, quantity = 0.f, seg_c0 = 0.f, last_w = 0.f;
    int seg_t0 = 0, r = 0;

    for (int chunk = 0; chunk < T_DIM; chunk += 32) {
        float wv = g_w[(chunk + lane) * B_DIM + b];
        float mymark = 0.f;
#pragma unroll 1
        for (int j = 0; j < 32; j++) {
            const int t = chunk + j;
            float w = __shfl_sync(0xffffffffu, wv, j);
            float mark = 0.f;
            if (t < L) {
                quantity += w;
                if (t == 0) seg_c0 = w;
                bool fired = (prev_w + w >= 1.0f);
                if (fired) {
                    float remained = 1.0f - prev_w;
                    if (lane == 0) {
                        int idx = b * T_DIM + r;
                        g_rt0[idx] = seg_t0; g_rt1[idx] = t;
                        g_rc0[idx] = seg_c0; g_rc1[idx] = remained;
                        g_rmult[idx] = 1.0f;
                    }
                    r++;
                    prev_w = w - remained;
                    seg_t0 = t;
                    seg_c0 = w - remained;
                    mark = 1.f;
                } else {
                    prev_w = w + prev_w;
                }
                last_w = w;
            } else if (t == L) {
                if (prev_w > 0.6f) {
                    if (lane == 0) {
                        int idx = b * T_DIM + r;
                        g_rt0[idx] = seg_t0; g_rt1[idx] = L - 1;
                        g_rc0[idx] = seg_c0; g_rc1[idx] = last_w;
                        g_rmult[idx] = 1.0f / (prev_w + 1e-10f);
                    }
                    r++;
                    mark = 1.f;
                }
            }
            if (lane == j) mymark = mark;
        }
        if (write_extras) out_marks[b * T_DIM + chunk + lane] = mymark;
    }
    if (lane == 0) {
        g_nrows[b] = r;
        if (write_extras) out_quantity[b] = quantity;
    }
}

// ---------------- K3: segment sums in compacted order -----------------------
__global__ __launch_bounds__(128) void k3_rows(
    const float* __restrict__ x,
    float* __restrict__ out_cif,
    float* __restrict__ out_mask,
    int write_extras)
{
    const int r = blockIdx.x, b = blockIdx.y;
    const int tid = threadIdx.x;
    const int nr = g_nrows[b];

    float4 acc = make_float4(0.f, 0.f, 0.f, 0.f);
    if (r < nr) {
        const int idx = b * T_DIM + r;
        const int t0 = g_rt0[idx], t1 = g_rt1[idx];
        const float c0 = g_rc0[idx], c1 = g_rc1[idx], mult = g_rmult[idx];
        const float* xb = x + (size_t)b * E_DIM + tid * 4;
        const size_t tstride = (size_t)B_DIM * E_DIM;

        float4 v = *(const float4*)(xb + (size_t)t0 * tstride);
        acc.x = c0 * v.x; acc.y = c0 * v.y; acc.z = c0 * v.z; acc.w = c0 * v.w;
        for (int t = t0 + 1; t < t1; t++) {
            float w = g_w[t * B_DIM + b];
            v = *(const float4*)(xb + (size_t)t * tstride);
            acc.x = fmaf(w, v.x, acc.x); acc.y = fmaf(w, v.y, acc.y);
            acc.z = fmaf(w, v.z, acc.z); acc.w = fmaf(w, v.w, acc.w);
        }
        if (t1 > t0) {
            v = *(const float4*)(xb + (size_t)t1 * tstride);
            acc.x = fmaf(c1, v.x, acc.x); acc.y = fmaf(c1, v.y, acc.y);
            acc.z = fmaf(c1, v.z, acc.z); acc.w = fmaf(c1, v.w, acc.w);
        }
        acc.x *= mult; acc.y *= mult; acc.z *= mult; acc.w *= mult;
    }
    *(float4*)(out_cif + ((size_t)(b * T_DIM + r)) * E_DIM + tid * 4) = acc;
    if (write_extras && tid == 0) out_mask[b * T_DIM + r] = (r < nr) ? 1.f : 0.f;
}

// ---------------- launch ----------------------------------------------------
extern "C" void kernel_launch(void* const* d_in, const int* in_sizes, int n_in,
                              void* d_out, int out_size)
{
    const float* enc = (const float*)d_in[0];
    const void*  mask = d_in[1];
    const float* dense_w = (const float*)d_in[2];
    const float* dense_b = (const float*)d_in[3];
    const float* wproj_w = (const float*)d_in[4];
    const float* wproj_b = (const float*)d_in[5];
    float* out = (float*)d_out;

    const int cif_elems = B_DIM * T_DIM * E_DIM;
    const int full = cif_elems + B_DIM * T_DIM + B_DIM + B_DIM * T_DIM;
    const int extras = (out_size >= full) ? 1 : 0;

    float* out_mask   = out + cif_elems;
    float* out_q      = out_mask + B_DIM * T_DIM;
    float* out_marks  = out_q + B_DIM;

    cudaFuncSetAttribute(k1_gemm, cudaFuncAttributeMaxDynamicSharedMemorySize, SM_BYTES);

    k0_mask<<<1, 1024>>>(mask);
    k1_gemm<<<M_DIM / BMT, 256, SM_BYTES>>>(enc, dense_w, dense_b, wproj_w, wproj_b);
    k2_scan<<<B_DIM, 32>>>(out_marks, out_q, extras);
    k3_rows<<<dim3(T_DIM, B_DIM), 128>>>(enc, out, out_mask, extras);
}

// round 8
// speedup vs baseline: 1.3465x; 1.3465x over previous
#include <cuda_runtime.h>
#include <cstdint>
#include <cstddef>

#define T_DIM 2048
#define B_DIM 32
#define E_DIM 512
#define N_DIM 512
#define K_DIM 512
#define M_DIM (T_DIM * B_DIM)   // 65536 rows, row m = t*B + b

// ---------------- device scratch ----------------
__device__ float g_w[M_DIM];
__device__ int   g_len[B_DIM];
__device__ int   g_nrows[B_DIM];
__device__ int   g_rt0[B_DIM * T_DIM];
__device__ int   g_rt1[B_DIM * T_DIM];
__device__ float g_rc0[B_DIM * T_DIM];
__device__ float g_rc1[B_DIM * T_DIM];
__device__ float g_rmult[B_DIM * T_DIM];

// ---------------- f32x2 helpers ----------------
typedef unsigned long long u64;
__device__ __forceinline__ u64 fma2(u64 a, u64 b, u64 c) {
    u64 d;
    asm("fma.rn.f32x2 %0, %1, %2, %3;" : "=l"(d) : "l"(a), "l"(b), "l"(c));
    return d;
}
__device__ __forceinline__ u64 dupf(float a) {
    u64 d;
    asm("mov.b64 %0, {%1, %1};" : "=l"(d) : "f"(a));
    return d;
}
__device__ __forceinline__ void unpk(u64 v, float& lo, float& hi) {
    asm("mov.b64 {%0, %1}, %2;" : "=f"(lo), "=f"(hi) : "l"(v));
}

// ---------------- K0: mask dtype detection + lengths ------------------------
__global__ void k0_mask(const void* __restrict__ mask) {
    __shared__ int flags[3];
    int tid = threadIdx.x;
    if (tid < 3) flags[tid] = 0;
    __syncthreads();
    const unsigned* dw = (const unsigned*)mask;
    for (int i = tid; i < 16384; i += blockDim.x) {
        unsigned d = dw[i];
        if (d != 0u) {
            if (d == 1u)                flags[0] = 1;
            else if (d == 0x3F800000u)  flags[1] = 1;
            else                        flags[2] = 1;
        }
    }
    __syncthreads();
    int kind = flags[2] ? 2 : (flags[1] ? 1 : 0);
    int warp = tid >> 5, lane = tid & 31;
    int cnt = 0;
    if (kind == 2) {
        const unsigned char* p = (const unsigned char*)mask + warp * T_DIM;
        for (int t = lane; t < T_DIM; t += 32) cnt += (p[t] == 0);
    } else {
        const unsigned* p = dw + (size_t)warp * T_DIM;
        for (int t = lane; t < T_DIM; t += 32) cnt += (p[t] == 0u);
    }
    for (int o = 16; o > 0; o >>= 1) cnt += __shfl_down_sync(0xffffffffu, cnt, o);
    if (lane == 0) g_len[warp] = cnt;
}

// ---------------- K1: fused fp32 GEMM + ReLU + proj + sigmoid ---------------
// CTA (x, b): rows t in [128x, 128x+128) for batch b; early-exit if the whole
// tile is padding (t >= len[b]). Inner microkernel = best-measured R6 variant.
#define BMT 128
#define BNT 128
#define BKT 16
#define KTILES (K_DIM / BKT)   // 32
#define AS_STR (BMT + 4)

__global__ __launch_bounds__(256, 2) void k1_gemm(
    const float* __restrict__ A,   // [T][B][E]; row(t,b) at ((t*B)+b)*E
    const float* __restrict__ W1,  // [K][N] row-major
    const float* __restrict__ b1,  // [N]
    const float* __restrict__ w2,  // [N]
    const float* __restrict__ b2)  // [1]
{
    const int b = blockIdx.y;
    const int t0 = blockIdx.x * BMT;
    if (t0 >= g_len[b]) return;   // whole tile is padding: weights never read

    __shared__ float As[2][BKT][AS_STR];
    __shared__ __align__(16) float Bs[2][BKT][BNT];
    __shared__ float red[BMT][17];

    const int tid = threadIdx.x;
    const int tx = tid & 15, ty = tid >> 4;

    const int aRow0 = tid >> 2;
    const int aRow1 = aRow0 + 64;
    const int aCol  = (tid & 3) * 4;
    const int bRow0 = tid >> 5;
    const int bRow1 = bRow0 + 8;
    const int bCol  = (tid & 31) * 4;

    // global row base addresses for this CTA's two loader rows
    const float* aP0 = A + ((size_t)(t0 + aRow0) * B_DIM + b) * K_DIM + aCol;
    const float* aP1 = A + ((size_t)(t0 + aRow1) * B_DIM + b) * K_DIM + aCol;

    float rowacc[8];
#pragma unroll
    for (int i = 0; i < 8; i++) rowacc[i] = 0.f;
    const float b2s = b2[0];

    for (int n0 = 0; n0 < N_DIM; n0 += BNT) {
        u64 acc2[8][4];
#pragma unroll
        for (int i = 0; i < 8; i++)
#pragma unroll
            for (int j = 0; j < 4; j++) acc2[i][j] = 0ull;

        float4 aR0, aR1, bR0, bR1;
        aR0 = *(const float4*)(aP0);
        aR1 = *(const float4*)(aP1);
        bR0 = *(const float4*)(W1 + (size_t)bRow0 * N_DIM + n0 + bCol);
        bR1 = *(const float4*)(W1 + (size_t)bRow1 * N_DIM + n0 + bCol);
        As[0][aCol + 0][aRow0] = aR0.x; As[0][aCol + 1][aRow0] = aR0.y;
        As[0][aCol + 2][aRow0] = aR0.z; As[0][aCol + 3][aRow0] = aR0.w;
        As[0][aCol + 0][aRow1] = aR1.x; As[0][aCol + 1][aRow1] = aR1.y;
        As[0][aCol + 2][aRow1] = aR1.z; As[0][aCol + 3][aRow1] = aR1.w;
        *(float4*)&Bs[0][bRow0][bCol] = bR0;
        *(float4*)&Bs[0][bRow1][bCol] = bR1;
        __syncthreads();

        for (int kt = 0; kt < KTILES; kt++) {
            const int cur = kt & 1;
            if (kt + 1 < KTILES) {
                const int kb = (kt + 1) * BKT;
                aR0 = *(const float4*)(aP0 + kb);
                aR1 = *(const float4*)(aP1 + kb);
                bR0 = *(const float4*)(W1 + (size_t)(kb + bRow0) * N_DIM + n0 + bCol);
                bR1 = *(const float4*)(W1 + (size_t)(kb + bRow1) * N_DIM + n0 + bCol);
            }
#pragma unroll
            for (int kk = 0; kk < BKT; kk++) {
                float4 a0 = *(const float4*)&As[cur][kk][ty * 8];
                float4 a1 = *(const float4*)&As[cur][kk][ty * 8 + 4];
                const u64* bp = (const u64*)&Bs[cur][kk][tx * 8];
                u64 b0 = bp[0], b1v = bp[1], b2v = bp[2], b3 = bp[3];
                float av[8] = {a0.x, a0.y, a0.z, a0.w, a1.x, a1.y, a1.z, a1.w};
#pragma unroll
                for (int i = 0; i < 8; i++) {
                    u64 ad = dupf(av[i]);
                    acc2[i][0] = fma2(ad, b0,  acc2[i][0]);
                    acc2[i][1] = fma2(ad, b1v, acc2[i][1]);
                    acc2[i][2] = fma2(ad, b2v, acc2[i][2]);
                    acc2[i][3] = fma2(ad, b3,  acc2[i][3]);
                }
            }
            if (kt + 1 < KTILES) {
                const int nb = cur ^ 1;
                As[nb][aCol + 0][aRow0] = aR0.x; As[nb][aCol + 1][aRow0] = aR0.y;
                As[nb][aCol + 2][aRow0] = aR0.z; As[nb][aCol + 3][aRow0] = aR0.w;
                As[nb][aCol + 0][aRow1] = aR1.x; As[nb][aCol + 1][aRow1] = aR1.y;
                As[nb][aCol + 2][aRow1] = aR1.z; As[nb][aCol + 3][aRow1] = aR1.w;
                *(float4*)&Bs[nb][bRow0][bCol] = bR0;
                *(float4*)&Bs[nb][bRow1][bCol] = bR1;
                __syncthreads();
            }
        }

        float b1r[8], w2r[8];
#pragma unroll
        for (int j = 0; j < 8; j++) {
            b1r[j] = b1[n0 + tx * 8 + j];
            w2r[j] = w2[n0 + tx * 8 + j];
        }
#pragma unroll
        for (int i = 0; i < 8; i++)
#pragma unroll
            for (int j2 = 0; j2 < 4; j2++) {
                float clo, chi;
                unpk(acc2[i][j2], clo, chi);
                float h0 = fmaxf(clo + b1r[j2 * 2], 0.f);
                float h1 = fmaxf(chi + b1r[j2 * 2 + 1], 0.f);
                rowacc[i] = fmaf(h0, w2r[j2 * 2], rowacc[i]);
                rowacc[i] = fmaf(h1, w2r[j2 * 2 + 1], rowacc[i]);
            }
        __syncthreads();
    }

    // reduce rowacc across the 16 tx threads of each row (fixed order)
#pragma unroll
    for (int i = 0; i < 8; i++) red[ty * 8 + i][tx] = rowacc[i];
    __syncthreads();
    if (tid < BMT) {
        float s = 0.f;
#pragma unroll
        for (int x = 0; x < 16; x++) s += red[tid][x];
        float arg = s + b2s;
        g_w[(size_t)(t0 + tid) * B_DIM + b] = 1.0f / (1.0f + expf(-arg));
    }
}

// ---------------- K2: scalar CIF scan per batch -----------------------------
__global__ void k2_scan(float* __restrict__ out_marks,
                        float* __restrict__ out_quantity,
                        int write_extras)
{
    const int b = blockIdx.x;
    const int lane = threadIdx.x;
    const int L = g_len[b];

    float prev_w = 0.f, quantity = 0.f, seg_c0 = 0.f, last_w = 0.f;
    int seg_t0 = 0, r = 0;

    for (int chunk = 0; chunk < T_DIM; chunk += 32) {
        float wv = g_w[(chunk + lane) * B_DIM + b];
        float mymark = 0.f;
#pragma unroll 1
        for (int j = 0; j < 32; j++) {
            const int t = chunk + j;
            float w = __shfl_sync(0xffffffffu, wv, j);
            float mark = 0.f;
            if (t < L) {
                quantity += w;
                if (t == 0) seg_c0 = w;
                bool fired = (prev_w + w >= 1.0f);
                if (fired) {
                    float remained = 1.0f - prev_w;
                    if (lane == 0) {
                        int idx = b * T_DIM + r;
                        g_rt0[idx] = seg_t0; g_rt1[idx] = t;
                        g_rc0[idx] = seg_c0; g_rc1[idx] = remained;
                        g_rmult[idx] = 1.0f;
                    }
                    r++;
                    prev_w = w - remained;
                    seg_t0 = t;
                    seg_c0 = w - remained;
                    mark = 1.f;
                } else {
                    prev_w = w + prev_w;
                }
                last_w = w;
            } else if (t == L) {
                if (prev_w > 0.6f) {
                    if (lane == 0) {
                        int idx = b * T_DIM + r;
                        g_rt0[idx] = seg_t0; g_rt1[idx] = L - 1;
                        g_rc0[idx] = seg_c0; g_rc1[idx] = last_w;
                        g_rmult[idx] = 1.0f / (prev_w + 1e-10f);
                    }
                    r++;
                    mark = 1.f;
                }
            }
            if (lane == j) mymark = mark;
        }
        if (write_extras) out_marks[b * T_DIM + chunk + lane] = mymark;
    }
    if (lane == 0) {
        g_nrows[b] = r;
        if (write_extras) out_quantity[b] = quantity;
    }
}

// ---------------- K3: segment sums in compacted order -----------------------
__global__ __launch_bounds__(128) void k3_rows(
    const float* __restrict__ x,
    float* __restrict__ out_cif,
    float* __restrict__ out_mask,
    int write_extras)
{
    const int r = blockIdx.x, b = blockIdx.y;
    const int tid = threadIdx.x;
    const int nr = g_nrows[b];

    float4 acc = make_float4(0.f, 0.f, 0.f, 0.f);
    if (r < nr) {
        const int idx = b * T_DIM + r;
        const int t0 = g_rt0[idx], t1 = g_rt1[idx];
        const float c0 = g_rc0[idx], c1 = g_rc1[idx], mult = g_rmult[idx];
        const float* xb = x + (size_t)b * E_DIM + tid * 4;
        const size_t tstride = (size_t)B_DIM * E_DIM;

        float4 v = *(const float4*)(xb + (size_t)t0 * tstride);
        acc.x = c0 * v.x; acc.y = c0 * v.y; acc.z = c0 * v.z; acc.w = c0 * v.w;
        for (int t = t0 + 1; t < t1; t++) {
            float w = g_w[t * B_DIM + b];
            v = *(const float4*)(xb + (size_t)t * tstride);
            acc.x = fmaf(w, v.x, acc.x); acc.y = fmaf(w, v.y, acc.y);
            acc.z = fmaf(w, v.z, acc.z); acc.w = fmaf(w, v.w, acc.w);
        }
        if (t1 > t0) {
            v = *(const float4*)(xb + (size_t)t1 * tstride);
            acc.x = fmaf(c1, v.x, acc.x); acc.y = fmaf(c1, v.y, acc.y);
            acc.z = fmaf(c1, v.z, acc.z); acc.w = fmaf(c1, v.w, acc.w);
        }
        acc.x *= mult; acc.y *= mult; acc.z *= mult; acc.w *= mult;
    }
    *(float4*)(out_cif + ((size_t)(b * T_DIM + r)) * E_DIM + tid * 4) = acc;
    if (write_extras && tid == 0) out_mask[b * T_DIM + r] = (r < nr) ? 1.f : 0.f;
}

// ---------------- launch ----------------------------------------------------
extern "C" void kernel_launch(void* const* d_in, const int* in_sizes, int n_in,
                              void* d_out, int out_size)
{
    const float* enc = (const float*)d_in[0];
    const void*  mask = d_in[1];
    const float* dense_w = (const float*)d_in[2];
    const float* dense_b = (const float*)d_in[3];
    const float* wproj_w = (const float*)d_in[4];
    const float* wproj_b = (const float*)d_in[5];
    float* out = (float*)d_out;

    const int cif_elems = B_DIM * T_DIM * E_DIM;
    const int full = cif_elems + B_DIM * T_DIM + B_DIM + B_DIM * T_DIM;
    const int extras = (out_size >= full) ? 1 : 0;

    float* out_mask   = out + cif_elems;
    float* out_q      = out_mask + B_DIM * T_DIM;
    float* out_marks  = out_q + B_DIM;

    k0_mask<<<1, 1024>>>(mask);
    k1_gemm<<<dim3(T_DIM / BMT, B_DIM), 256>>>(enc, dense_w, dense_b, wproj_w, wproj_b);
    k2_scan<<<B_DIM, 32>>>(out_marks, out_q, extras);
    k3_rows<<<dim3(T_DIM, B_DIM), 128>>>(enc, out, out_mask, extras);
}